// round 2
// baseline (speedup 1.0000x reference)
#include <cuda_runtime.h>
#include <cuda_bf16.h>

// 4096-pt FWHT, 8192 rows fp32.  Radix 64x64 decomposition:
//   Round A butterflies element bits [7:2]   (thread owns bits {[11:8],[1:0]})
//   Round B butterflies element bits {[11:8],[1:0]} (thread owns bits [7:2])
// All 12 butterfly bits covered; stages commute, so order/grouping is free.
// 64 threads per row, 2 rows per 128-thread CTA.
// Global: only coalesced LDG.128 / STG.128. Shared: skew phys(e)=e+(e>>8)*4,
// all four access patterns bank-conflict-free. Math: packed fma.rn.f32x2.

#define ROW   4096
#define TPR   64          // threads per row
#define RPB   2           // rows per block
#define NT    (TPR*RPB)   // 128
#define SROW  4160        // padded words per row (max phys 4155, round to /16B)

__device__ __forceinline__ float2 ffma2(float2 b, float2 m, float2 a) {
    float2 r;
    asm("fma.rn.f32x2 %0, %1, %2, %3;"
        : "=l"(reinterpret_cast<unsigned long long&>(r))
        : "l"(reinterpret_cast<const unsigned long long&>(b)),
          "l"(reinterpret_cast<const unsigned long long&>(m)),
          "l"(reinterpret_cast<const unsigned long long&>(a)));
    return r;
}

__device__ __forceinline__ float2 fmul2(float2 a, float2 m) {
    float2 r;
    asm("mul.rn.f32x2 %0, %1, %2;"
        : "=l"(reinterpret_cast<unsigned long long&>(r))
        : "l"(reinterpret_cast<const unsigned long long&>(a)),
          "l"(reinterpret_cast<const unsigned long long&>(m)));
    return r;
}

// fwht over 64 values held as 32 packed float2 (v[p] = (elem 2p, elem 2p+1)).
__device__ __forceinline__ void fwht64p(float2* v) {
    const float2 P1 = make_float2(1.0f, 1.0f);
    const float2 M1 = make_float2(-1.0f, -1.0f);
    // h=1 stage: intra-pair butterfly (scalar adds)
#pragma unroll
    for (int p = 0; p < 32; p++) {
        float lo = v[p].x, hi = v[p].y;
        v[p].x = lo + hi;
        v[p].y = lo - hi;
    }
    // h=2..64 stages: packed butterflies over p-index
#pragma unroll
    for (int h = 1; h < 32; h <<= 1) {
#pragma unroll
        for (int p = 0; p < 32; p++) {
            if ((p & h) == 0) {
                float2 a = v[p], b = v[p + h];
                v[p]     = ffma2(b, P1, a);   // a + b
                v[p + h] = ffma2(b, M1, a);   // a - b
            }
        }
    }
}

__global__ void __launch_bounds__(NT, 4)
fwht4096_kernel(const float* __restrict__ in, float* __restrict__ out) {
    __shared__ __align__(16) float s[RPB * SROW];

    const int tid = threadIdx.x;
    const int rb  = tid / TPR;        // row within block
    const int t   = tid % TPR;        // thread within row, 0..63
    const size_t row = (size_t)blockIdx.x * RPB + rb;

    const float4* __restrict__ x4 = reinterpret_cast<const float4*>(in + row * ROW);
    float4* __restrict__       y4 = reinterpret_cast<float4*>(out + row * ROW);
    float* sm = s + rb * SROW;

    // ---- Stage: coalesced vector load -> staged to smem.
    // float4 index q = i*64 + t  (lanes consecutive -> 512B coalesced).
    // element e = 4q = 256*i + 4*t ; phys = e + (e>>8)*4 = 260*i + 4*t (16B aligned).
#pragma unroll
    for (int i = 0; i < 16; i++) {
        float4 q = x4[i * 64 + t];
        *reinterpret_cast<float4*>(sm + 260 * i + 4 * t) = q;
    }
    __syncthreads();

    // ---- Round A: thread (j,r), j=t>>2, r=t&3 owns e = j*256 + m*4 + r, m=0..63.
    // Gather: word 260*j + 4*m + r. Per-instr banks (4j+r) mod 32 -> conflict-free.
    {
        const int j = t >> 2, r = t & 3;
        const float* base = sm + 260 * j + r;
        float2 v[32];
#pragma unroll
        for (int p = 0; p < 32; p++) {
            float a = base[4 * (2 * p)];
            float b = base[4 * (2 * p + 1)];
            v[p] = make_float2(a, b);
        }
        fwht64p(v);   // butterflies e bits [7:2]

        // Scatter back to the SAME addresses this thread read (self-owned set,
        // no barrier needed before the writes).
        float* wbase = sm + 260 * j + r;
#pragma unroll
        for (int p = 0; p < 32; p++) {
            wbase[4 * (2 * p)]     = v[p].x;
            wbase[4 * (2 * p + 1)] = v[p].y;
        }
    }
    __syncthreads();

    // ---- Round B: thread t owns e = jj*256 + t*4 + rr (jj=0..15, rr=0..3),
    // reg idx = jj*4 + rr. Vector gather: word 260*jj + 4*t (+rr) -> LDS.128,
    // banks 4*lane per phase -> conflict-free.
    {
        float2 w[32];
#pragma unroll
        for (int jj = 0; jj < 16; jj++) {
            float4 q = *reinterpret_cast<const float4*>(sm + 260 * jj + 4 * t);
            w[2 * jj]     = make_float2(q.x, q.y);
            w[2 * jj + 1] = make_float2(q.z, q.w);
        }
        fwht64p(w);   // butterflies e bits {[11:8],[1:0]}

        // Scale by 1/sqrt(4096) = 1/64 and store: float4 index q = jj*64 + t
        // -> fully coalesced STG.128.
        const float2 SC = make_float2(1.0f / 64.0f, 1.0f / 64.0f);
#pragma unroll
        for (int jj = 0; jj < 16; jj++) {
            float2 lo = fmul2(w[2 * jj], SC);
            float2 hi = fmul2(w[2 * jj + 1], SC);
            float4 o;
            o.x = lo.x; o.y = lo.y; o.z = hi.x; o.w = hi.y;
            y4[jj * 64 + t] = o;
        }
    }
}

extern "C" void kernel_launch(void* const* d_in, const int* in_sizes, int n_in,
                              void* d_out, int out_size) {
    const float* x = (const float*)d_in[0];
    float* y = (float*)d_out;
    int total = in_sizes[0];
    int nrows = total / ROW;            // 8192
    fwht4096_kernel<<<nrows / RPB, NT>>>(x, y);
}

// round 4
// speedup vs baseline: 1.3925x; 1.3925x over previous
#include <cuda_runtime.h>
#include <cuda_bf16.h>
#include <cstdint>

// 4096-pt FWHT, 8192 rows fp32.
// Radix 64x64: Round A butterflies element bits [7:2], Round B bits {[11:8],[1:0]}.
// One 64-thread CTA processes rows_per_cta rows, software-pipelined:
// cp.async.cg streams row k+1 into smem buffer (k+1)&1 while row k is computed
// from buffer k&1. Skewed smem (phys = e + (e>>8)*4) keeps every access pattern
// bank-conflict-free. Packed fma.rn.f32x2 butterflies. Coalesced LDGSTS/STG.128.

#define ROW    4096
#define TPR    64            // threads per CTA (= per row)
#define SROW   4160          // skewed row words (max phys 4155, pad to 16B mult)
#define NCTAS  1024          // rows-per-CTA = total_rows / NCTAS

__device__ __forceinline__ float2 ffma2(float2 b, float2 m, float2 a) {
    float2 r;
    asm("fma.rn.f32x2 %0, %1, %2, %3;"
        : "=l"(reinterpret_cast<unsigned long long&>(r))
        : "l"(reinterpret_cast<const unsigned long long&>(b)),
          "l"(reinterpret_cast<const unsigned long long&>(m)),
          "l"(reinterpret_cast<const unsigned long long&>(a)));
    return r;
}

__device__ __forceinline__ float2 fmul2(float2 a, float2 m) {
    float2 r;
    asm("mul.rn.f32x2 %0, %1, %2;"
        : "=l"(reinterpret_cast<unsigned long long&>(r))
        : "l"(reinterpret_cast<const unsigned long long&>(a)),
          "l"(reinterpret_cast<const unsigned long long&>(m)));
    return r;
}

// 64-pt FWHT over 32 packed float2 (v[p] = (elem 2p, elem 2p+1)).
__device__ __forceinline__ void fwht64p(float2* v) {
    const float2 P1 = make_float2(1.0f, 1.0f);
    const float2 M1 = make_float2(-1.0f, -1.0f);
#pragma unroll
    for (int p = 0; p < 32; p++) {           // h=1 (intra-pair)
        float lo = v[p].x, hi = v[p].y;
        v[p].x = lo + hi;
        v[p].y = lo - hi;
    }
#pragma unroll
    for (int h = 1; h < 32; h <<= 1) {       // h=2..64 packed
#pragma unroll
        for (int p = 0; p < 32; p++) {
            if ((p & h) == 0) {
                float2 a = v[p], b = v[p + h];
                v[p]     = ffma2(b, P1, a);
                v[p + h] = ffma2(b, M1, a);
            }
        }
    }
}

__device__ __forceinline__ void cp_async16(uint32_t dst_smem, const void* src) {
    asm volatile("cp.async.cg.shared.global [%0], [%1], 16;"
                 :: "r"(dst_smem), "l"(src) : "memory");
}
__device__ __forceinline__ void cp_commit() {
    asm volatile("cp.async.commit_group;" ::: "memory");
}
template <int N>
__device__ __forceinline__ void cp_wait() {
    asm volatile("cp.async.wait_group %0;" :: "n"(N) : "memory");
}

// Stage one row into a smem buffer: float4 q = i*64 + t (coalesced),
// element e = 256*i + 4*t -> skewed word 260*i + 4*t (16B aligned).
__device__ __forceinline__ void stage_row(uint32_t sbuf, const float4* x4, int t) {
#pragma unroll
    for (int i = 0; i < 16; i++)
        cp_async16(sbuf + (260u * i + 4u * t) * 4u, x4 + i * 64 + t);
    cp_commit();
}

__global__ void __launch_bounds__(TPR)
fwht4096_kernel(const float* __restrict__ in, float* __restrict__ out, int rows_per_cta) {
    __shared__ __align__(16) float s[2 * SROW];

    const int t = threadIdx.x;
    const long row0 = (long)blockIdx.x * rows_per_cta;

    uint32_t sbase;
    asm("{ .reg .u64 tmp; cvta.to.shared.u64 tmp, %1; cvt.u32.u64 %0, tmp; }"
        : "=r"(sbase) : "l"(s));
    const uint32_t sbuf0 = sbase;
    const uint32_t sbuf1 = sbase + SROW * 4u;

    // Prologue: prefetch row 0 into buffer 0.
    stage_row(sbuf0, reinterpret_cast<const float4*>(in + row0 * ROW), t);

    const int j = t >> 2, r = t & 3;   // round-A ownership

    for (int k = 0; k < rows_per_cta; k++) {
        const int cur = k & 1;
        // Prefetch next row into the other buffer (previous iteration's trailing
        // barrier guarantees nobody still reads it).
        if (k + 1 < rows_per_cta) {
            stage_row(cur ? sbuf0 : sbuf1,
                      reinterpret_cast<const float4*>(in + (row0 + k + 1) * ROW), t);
            cp_wait<1>();   // current row's group complete
        } else {
            cp_wait<0>();
        }
        __syncthreads();

        float* sm = s + cur * SROW;

        // ---- Round A: thread (j,r) owns e = j*256 + m*4 + r, m = 0..63.
        // Skewed word = 260*j + 4*m + r; banks (4j+r) mod 32 per phase -> clean.
        {
            float* base = sm + 260 * j + r;
            float2 v[32];
#pragma unroll
            for (int p = 0; p < 32; p++)
                v[p] = make_float2(base[8 * p], base[8 * p + 4]);
            fwht64p(v);   // butterflies bits [7:2]
#pragma unroll
            for (int p = 0; p < 32; p++) {
                base[8 * p]     = v[p].x;
                base[8 * p + 4] = v[p].y;
            }
        }
        __syncthreads();

        // ---- Round B: thread t owns e = jj*256 + 4*t + rr (LDS.128 gather),
        // butterflies bits {[11:8],[1:0]}, then scaled coalesced STG.128.
        {
            float2 w[32];
#pragma unroll
            for (int jj = 0; jj < 16; jj++) {
                float4 q = *reinterpret_cast<const float4*>(sm + 260 * jj + 4 * t);
                w[2 * jj]     = make_float2(q.x, q.y);
                w[2 * jj + 1] = make_float2(q.z, q.w);
            }
            fwht64p(w);

            const float2 SC = make_float2(1.0f / 64.0f, 1.0f / 64.0f);
            float4* y4 = reinterpret_cast<float4*>(out + (row0 + k) * ROW);
#pragma unroll
            for (int jj = 0; jj < 16; jj++) {
                float2 lo = fmul2(w[2 * jj], SC);
                float2 hi = fmul2(w[2 * jj + 1], SC);
                float4 o;
                o.x = lo.x; o.y = lo.y; o.z = hi.x; o.w = hi.y;
                y4[jj * 64 + t] = o;
            }
        }
        // Protect buffer cur before next iteration's prefetch overwrites it.
        __syncthreads();
    }
}

extern "C" void kernel_launch(void* const* d_in, const int* in_sizes, int n_in,
                              void* d_out, int out_size) {
    const float* x = (const float*)d_in[0];
    float* y = (float*)d_out;
    int total = in_sizes[0];
    int nrows = total / ROW;                      // 8192
    int nctas = NCTAS;
    if (nrows % nctas != 0) nctas = nrows;        // fallback: 1 row per CTA
    int rpc = nrows / nctas;
    fwht4096_kernel<<<nctas, TPR>>>(x, y, rpc);
}